// round 4
// baseline (speedup 1.0000x reference)
#include <cuda_runtime.h>
#include <cuda_bf16.h>
#include <cstdint>

// Problem constants
#define BATCH 16
#define NN    1024
#define FF    128
#define GTOT  (BATCH * NN)     // 16384

// ---------------------------------------------------------------------------
// Device-global scratch (no allocations allowed)
// ---------------------------------------------------------------------------
__device__ float g_dinv[GTOT];              // 64 KB
__device__ float g_YsT[FF * GTOT];          // 8 MB  [f][g]  tf32-rounded, d_m-scaled
__device__ float g_Ysn[GTOT * FF];          // 8 MB  [g][f]  full fp32,   d_m-scaled

// ---------------------------------------------------------------------------
// Helpers
// ---------------------------------------------------------------------------
__device__ __forceinline__ uint32_t smem_to_u32(const void* p) {
    uint32_t a;
    asm("{ .reg .u64 t; cvta.to.shared.u64 t, %1; cvt.u32.u64 %0, t; }" : "=r"(a) : "l"(p));
    return a;
}
#define CP_ASYNC_16(dst_u32, src) \
    asm volatile("cp.async.cg.shared.global [%0], [%1], 16;" \
                 :: "r"(dst_u32), "l"(src) : "memory")
#define CP_ASYNC_COMMIT() asm volatile("cp.async.commit_group;" ::: "memory")
#define CP_ASYNC_WAIT(n)  asm volatile("cp.async.wait_group %0;" :: "n"(n) : "memory")

__device__ __forceinline__ uint32_t f32_to_tf32(float x) {
    uint32_t u;
    asm("cvt.rna.tf32.f32 %0, %1;" : "=r"(u) : "f"(x));
    return u;
}

__device__ __forceinline__ void mma_tf32(float* c, const uint32_t* a, const uint32_t* b) {
    asm volatile(
        "mma.sync.aligned.m16n8k8.row.col.f32.tf32.tf32.f32 "
        "{%0,%1,%2,%3}, {%4,%5,%6,%7}, {%8,%9}, {%0,%1,%2,%3};\n"
        : "+f"(c[0]), "+f"(c[1]), "+f"(c[2]), "+f"(c[3])
        : "r"(a[0]), "r"(a[1]), "r"(a[2]), "r"(a[3]), "r"(b[0]), "r"(b[1]));
}

// ---------------------------------------------------------------------------
// Kernel 1: dinv[row] = rsqrt( sum_m A[row, m] + 1 ).  Warp per row, MLP=8.
// ---------------------------------------------------------------------------
__global__ void __launch_bounds__(256) deg_kernel(const float* __restrict__ A) {
    const int row = blockIdx.x * 8 + (threadIdx.x >> 5);
    const int lid = threadIdx.x & 31;
    const float4* Ar = reinterpret_cast<const float4*>(A + (size_t)row * NN);
    float s = 0.f;
    #pragma unroll
    for (int i = 0; i < 8; i++) {
        float4 v = Ar[lid + i * 32];
        s += (v.x + v.y) + (v.z + v.w);
    }
    #pragma unroll
    for (int o = 16; o; o >>= 1) s += __shfl_xor_sync(0xFFFFFFFFu, s, o);
    if (lid == 0) g_dinv[row] = rsqrtf(s + 1.0f);
}

// ---------------------------------------------------------------------------
// Kernel 2: Ysd = d_m * (X @ W), written in BOTH layouts:
//   g_YsT[f][g]  tf32-rounded (MMA B operand, K-contiguous)
//   g_Ysn[g][f]  full fp32   (epilogue identity-add)
// Tile: 128 f x 128 g per block; grid.x = 128
// ---------------------------------------------------------------------------
__global__ void __launch_bounds__(256) gemm_xw_t(const float* __restrict__ X,
                                                 const float* __restrict__ W) {
    __shared__ float As[16][128];   // W slice:  As[kk][f]
    __shared__ float Bs[16][128];   // X^T slice: Bs[kk][m]

    const int tid = threadIdx.x;
    const int m0g = blockIdx.x * 128;
    const int f0 = (tid >> 4) * 8;
    const int m0 = (tid & 15) * 8;

    float acc[8][8];
    #pragma unroll
    for (int i = 0; i < 8; i++)
        #pragma unroll
        for (int j = 0; j < 8; j++) acc[i][j] = 0.f;

    for (int k0 = 0; k0 < FF; k0 += 16) {
        {   // W -> As
            int idx = tid * 8;
            int kk = idx >> 7;
            int f = idx & 127;
            const float* wp = W + (size_t)(k0 + kk) * FF + f;
            float4 w0 = *reinterpret_cast<const float4*>(wp);
            float4 w1 = *reinterpret_cast<const float4*>(wp + 4);
            *reinterpret_cast<float4*>(&As[kk][f]) = w0;
            *reinterpret_cast<float4*>(&As[kk][f + 4]) = w1;
        }
        {   // X -> Bs transposed
            int m = tid >> 1;
            int half = tid & 1;
            const float* xp = X + (size_t)(m0g + m) * FF + k0 + half * 8;
            float4 x0 = *reinterpret_cast<const float4*>(xp);
            float4 x1 = *reinterpret_cast<const float4*>(xp + 4);
            int kb = half * 8;
            Bs[kb + 0][m] = x0.x; Bs[kb + 1][m] = x0.y;
            Bs[kb + 2][m] = x0.z; Bs[kb + 3][m] = x0.w;
            Bs[kb + 4][m] = x1.x; Bs[kb + 5][m] = x1.y;
            Bs[kb + 6][m] = x1.z; Bs[kb + 7][m] = x1.w;
        }
        __syncthreads();
        #pragma unroll
        for (int kk = 0; kk < 16; kk++) {
            float rf[8], rm[8];
            #pragma unroll
            for (int i = 0; i < 8; i++) rf[i] = As[kk][f0 + i];
            #pragma unroll
            for (int j = 0; j < 8; j++) rm[j] = Bs[kk][m0 + j];
            #pragma unroll
            for (int i = 0; i < 8; i++)
                #pragma unroll
                for (int j = 0; j < 8; j++) acc[i][j] = fmaf(rf[i], rm[j], acc[i][j]);
        }
        __syncthreads();
    }

    float dm[8];
    #pragma unroll
    for (int j = 0; j < 8; j++) dm[j] = g_dinv[m0g + m0 + j];

    // g_YsT[f][g]  (tf32-rounded so the MMA needs no B conversion)
    #pragma unroll
    for (int i = 0; i < 8; i++) {
        uint32_t t[8];
        #pragma unroll
        for (int j = 0; j < 8; j++) t[j] = f32_to_tf32(acc[i][j] * dm[j]);
        size_t dst = (size_t)(f0 + i) * GTOT + m0g + m0;
        *reinterpret_cast<uint4*>(&g_YsT[dst])     = make_uint4(t[0], t[1], t[2], t[3]);
        *reinterpret_cast<uint4*>(&g_YsT[dst + 4]) = make_uint4(t[4], t[5], t[6], t[7]);
    }
    // g_Ysn[g][f]  (exact fp32 for epilogue identity-add)
    #pragma unroll
    for (int j = 0; j < 8; j++) {
        float4 u0, u1;
        u0.x = acc[0][j] * dm[j]; u0.y = acc[1][j] * dm[j];
        u0.z = acc[2][j] * dm[j]; u0.w = acc[3][j] * dm[j];
        u1.x = acc[4][j] * dm[j]; u1.y = acc[5][j] * dm[j];
        u1.z = acc[6][j] * dm[j]; u1.w = acc[7][j] * dm[j];
        size_t dst = (size_t)(m0g + m0 + j) * FF + f0;
        *reinterpret_cast<float4*>(&g_Ysn[dst])     = u0;
        *reinterpret_cast<float4*>(&g_Ysn[dst + 4]) = u1;
    }
}

// ---------------------------------------------------------------------------
// Kernel 3: out[b,n,:] = d_n * ( A[b,n,:] @ Ysd[b] + Ysd[b,n,:] )  via tf32 MMA
//   CTA 128x128, K-chunk 32, 3-stage cp.async pipeline (pure cp.async, no
//   conversions in the staging path).  8 warps = 2(m) x 4(n), warp tile 64x32.
// ---------------------------------------------------------------------------
#define PITCH 144                  // 128B row + 16B pad (conflict-free LDS)
#define TILE3 (128 * PITCH)        // 18432 per operand tile
#define STAGE (2 * TILE3)          // A + B
#define NSTG  3
#define SMEM3 (NSTG * STAGE)       // 110592

__global__ void __launch_bounds__(256, 1) gemm_mma(const float* __restrict__ A,
                                                   float* __restrict__ out) {
    extern __shared__ char sm[];
    const uint32_t sb = smem_to_u32(sm);

    const int tid = threadIdx.x;
    const int wid = tid >> 5, lane = tid & 31;
    const int g = lane >> 2, tig = lane & 3;
    const int wm = wid & 1, wn = wid >> 1;
    const int b = blockIdx.y;
    const int rowStart = blockIdx.x * 128;

    // cp.async mapping: thread covers row tid>>1, 64B half tid&1 of the 128B chunk row
    const int cr = tid >> 1;
    const int ch = tid & 1;
    const float* Ap = A + ((size_t)b * NN + rowStart + cr) * NN + ch * 16;
    const float* Bp = g_YsT + (size_t)cr * GTOT + (size_t)b * NN + ch * 16;
    const uint32_t dbase = sb + cr * PITCH + ch * 64;

    auto issue = [&](int kc) {
        const uint32_t dA = dbase + (kc % NSTG) * STAGE;
        const uint32_t dB = dA + TILE3;
        const float* pa = Ap + kc * 32;
        const float* pb = Bp + kc * 32;
        #pragma unroll
        for (int j = 0; j < 4; j++) {
            CP_ASYNC_16(dA + j * 16, pa + j * 4);
            CP_ASYNC_16(dB + j * 16, pb + j * 4);
        }
        CP_ASYNC_COMMIT();
    };

    float acc[4][4][4];
    #pragma unroll
    for (int i = 0; i < 4; i++)
        #pragma unroll
        for (int j = 0; j < 4; j++)
            #pragma unroll
            for (int k = 0; k < 4; k++) acc[i][j][k] = 0.f;

    issue(0);
    issue(1);

    for (int kc = 0; kc < NN / 32; kc++) {
        if (kc < NN / 32 - 1) { CP_ASYNC_WAIT(1); } else { CP_ASYNC_WAIT(0); }
        __syncthreads();
        if (kc + 2 < NN / 32) issue(kc + 2);

        char* Ab = sm + (kc % NSTG) * STAGE;
        char* Bb = Ab + TILE3;

        #pragma unroll
        for (int ks = 0; ks < 4; ks++) {
            const int kb = ks * 32 + tig * 4;   // byte offset of k = ks*8 + tig
            uint32_t af[4][4], bf2[4][2];
            #pragma unroll
            for (int mt = 0; mt < 4; mt++) {
                const uint32_t o = (wm * 64 + mt * 16 + g) * PITCH + kb;
                float x0 = *reinterpret_cast<float*>(Ab + o);
                float x1 = *reinterpret_cast<float*>(Ab + o + 8 * PITCH);
                float x2 = *reinterpret_cast<float*>(Ab + o + 16);
                float x3 = *reinterpret_cast<float*>(Ab + o + 8 * PITCH + 16);
                af[mt][0] = f32_to_tf32(x0);
                af[mt][1] = f32_to_tf32(x1);
                af[mt][2] = f32_to_tf32(x2);
                af[mt][3] = f32_to_tf32(x3);
            }
            #pragma unroll
            for (int nt = 0; nt < 4; nt++) {
                const uint32_t o = (wn * 32 + nt * 8 + g) * PITCH + kb;
                bf2[nt][0] = *reinterpret_cast<uint32_t*>(Bb + o);       // pre-rounded tf32
                bf2[nt][1] = *reinterpret_cast<uint32_t*>(Bb + o + 16);
            }
            #pragma unroll
            for (int mt = 0; mt < 4; mt++)
                #pragma unroll
                for (int nt = 0; nt < 4; nt++)
                    mma_tf32(acc[mt][nt], af[mt], bf2[nt]);
        }
    }

    // Epilogue: out = d_n * (acc + Ysd[n,:])   (identity term exact in fp32)
    #pragma unroll
    for (int mt = 0; mt < 4; mt++) {
        const int gr0 = b * NN + rowStart + wm * 64 + mt * 16 + g;
        const float d0 = g_dinv[gr0];
        const float d1 = g_dinv[gr0 + 8];
        const float* ys0 = g_Ysn + (size_t)gr0 * FF + wn * 32 + tig * 2;
        const float* ys1 = ys0 + (size_t)8 * FF;
        float* o0 = out + (size_t)gr0 * FF + wn * 32 + tig * 2;
        float* o1 = o0 + (size_t)8 * FF;
        #pragma unroll
        for (int nt = 0; nt < 4; nt++) {
            float2 y0 = *reinterpret_cast<const float2*>(ys0 + nt * 8);
            float2 y1 = *reinterpret_cast<const float2*>(ys1 + nt * 8);
            float2 v0, v1;
            v0.x = d0 * (acc[mt][nt][0] + y0.x);
            v0.y = d0 * (acc[mt][nt][1] + y0.y);
            v1.x = d1 * (acc[mt][nt][2] + y1.x);
            v1.y = d1 * (acc[mt][nt][3] + y1.y);
            *reinterpret_cast<float2*>(o0 + nt * 8) = v0;
            *reinterpret_cast<float2*>(o1 + nt * 8) = v1;
        }
    }
}

// ---------------------------------------------------------------------------
// kernel_launch
// ---------------------------------------------------------------------------
extern "C" void kernel_launch(void* const* d_in, const int* in_sizes, int n_in,
                              void* d_out, int out_size) {
    const float* X = (const float*)d_in[0];   // [16,1024,128]
    const float* A = (const float*)d_in[1];   // [16,1024,1024]
    const float* W = (const float*)d_in[2];   // [128,128]
    float* out = (float*)d_out;               // [16,1024,128]

    cudaFuncSetAttribute(gemm_mma, cudaFuncAttributeMaxDynamicSharedMemorySize, SMEM3);

    // 1) dinv = rsqrt(rowsum(A) + 1)
    deg_kernel<<<GTOT / 8, 256>>>(A);

    // 2) Ysd = d_m * (X @ W), dual layout (tf32 transposed + fp32 natural)
    gemm_xw_t<<<GTOT / 128, 256>>>(X, W);

    // 3) out = d_n * (A @ Ysd + Ysd[n,:])  via tf32 mma.sync
    {
        dim3 grid(NN / 128, BATCH);
        gemm_mma<<<grid, 256, SMEM3>>>(A, out);
    }
}

// round 6
// speedup vs baseline: 1.2433x; 1.2433x over previous
#include <cuda_runtime.h>
#include <cuda_fp16.h>
#include <cuda_bf16.h>
#include <cstdint>

// Problem constants
#define BATCH 16
#define NN    1024
#define FF    128
#define GTOT  (BATCH * NN)     // 16384

// ---------------------------------------------------------------------------
// Device-global scratch (no allocations allowed)
// ---------------------------------------------------------------------------
__device__ float  g_dinv[GTOT];             // 64 KB
__device__ __half g_YsT_h[FF * GTOT];       // 4 MB  [f][g]  fp16, d_m-scaled
__device__ float  g_Ysn[GTOT * FF];         // 8 MB  [g][f]  fp32, d_m-scaled (exact)

// ---------------------------------------------------------------------------
// Helpers
// ---------------------------------------------------------------------------
__device__ __forceinline__ uint32_t smem_to_u32(const void* p) {
    uint32_t a;
    asm("{ .reg .u64 t; cvta.to.shared.u64 t, %1; cvt.u32.u64 %0, t; }" : "=r"(a) : "l"(p));
    return a;
}
#define CP_ASYNC_16(dst_u32, src) \
    asm volatile("cp.async.cg.shared.global [%0], [%1], 16;" \
                 :: "r"(dst_u32), "l"(src) : "memory")
#define CP_ASYNC_COMMIT()  asm volatile("cp.async.commit_group;" ::: "memory")
#define CP_ASYNC_WAIT_ALL() asm volatile("cp.async.wait_group 0;" ::: "memory")

__device__ __forceinline__ void mma_f16(float* c, const uint32_t* a, const uint32_t* b) {
    asm volatile(
        "mma.sync.aligned.m16n8k16.row.col.f32.f16.f16.f32 "
        "{%0,%1,%2,%3}, {%4,%5,%6,%7}, {%8,%9}, {%0,%1,%2,%3};\n"
        : "+f"(c[0]), "+f"(c[1]), "+f"(c[2]), "+f"(c[3])
        : "r"(a[0]), "r"(a[1]), "r"(a[2]), "r"(a[3]), "r"(b[0]), "r"(b[1]));
}

// ---------------------------------------------------------------------------
// Kernel 1: dinv[row] = rsqrt( rowsum(A) + 1 ).  2 rows per warp, MLP=16.
// ---------------------------------------------------------------------------
__global__ void __launch_bounds__(256) deg_kernel(const float* __restrict__ A) {
    const int wid = threadIdx.x >> 5, lid = threadIdx.x & 31;
    const int row0 = blockIdx.x * 16 + wid * 2;
    const float4* r0 = reinterpret_cast<const float4*>(A + (size_t)row0 * NN);
    const float4* r1 = reinterpret_cast<const float4*>(A + (size_t)(row0 + 1) * NN);
    float s0 = 0.f, s1 = 0.f;
    #pragma unroll
    for (int i = 0; i < 8; i++) {
        float4 a = r0[lid + i * 32];
        float4 b = r1[lid + i * 32];
        s0 += (a.x + a.y) + (a.z + a.w);
        s1 += (b.x + b.y) + (b.z + b.w);
    }
    #pragma unroll
    for (int o = 16; o; o >>= 1) {
        s0 += __shfl_xor_sync(0xFFFFFFFFu, s0, o);
        s1 += __shfl_xor_sync(0xFFFFFFFFu, s1, o);
    }
    if (lid == 0) {
        g_dinv[row0]     = rsqrtf(s0 + 1.0f);
        g_dinv[row0 + 1] = rsqrtf(s1 + 1.0f);
    }
}

// ---------------------------------------------------------------------------
// Kernel 2: Ysd = d_m * (X @ W), dual layout:
//   g_YsT_h[f][g]  fp16      (MMA B operand, K-contiguous)
//   g_Ysn[g][f]    fp32      (epilogue identity-add, exact)
// Tile: 128 f x 128 g per block; grid.x = 128
// ---------------------------------------------------------------------------
__global__ void __launch_bounds__(256) gemm_xw_t(const float* __restrict__ X,
                                                 const float* __restrict__ W) {
    __shared__ float As[16][128];   // W slice:  As[kk][f]
    __shared__ float Bs[16][128];   // X^T slice: Bs[kk][m]

    const int tid = threadIdx.x;
    const int m0g = blockIdx.x * 128;
    const int f0 = (tid >> 4) * 8;
    const int m0 = (tid & 15) * 8;

    float acc[8][8];
    #pragma unroll
    for (int i = 0; i < 8; i++)
        #pragma unroll
        for (int j = 0; j < 8; j++) acc[i][j] = 0.f;

    for (int k0 = 0; k0 < FF; k0 += 16) {
        {   // W -> As
            int idx = tid * 8;
            int kk = idx >> 7;
            int f = idx & 127;
            const float* wp = W + (size_t)(k0 + kk) * FF + f;
            float4 w0 = *reinterpret_cast<const float4*>(wp);
            float4 w1 = *reinterpret_cast<const float4*>(wp + 4);
            *reinterpret_cast<float4*>(&As[kk][f]) = w0;
            *reinterpret_cast<float4*>(&As[kk][f + 4]) = w1;
        }
        {   // X -> Bs transposed
            int m = tid >> 1;
            int half = tid & 1;
            const float* xp = X + (size_t)(m0g + m) * FF + k0 + half * 8;
            float4 x0 = *reinterpret_cast<const float4*>(xp);
            float4 x1 = *reinterpret_cast<const float4*>(xp + 4);
            int kb = half * 8;
            Bs[kb + 0][m] = x0.x; Bs[kb + 1][m] = x0.y;
            Bs[kb + 2][m] = x0.z; Bs[kb + 3][m] = x0.w;
            Bs[kb + 4][m] = x1.x; Bs[kb + 5][m] = x1.y;
            Bs[kb + 6][m] = x1.z; Bs[kb + 7][m] = x1.w;
        }
        __syncthreads();
        #pragma unroll
        for (int kk = 0; kk < 16; kk++) {
            float rf[8], rm[8];
            #pragma unroll
            for (int i = 0; i < 8; i++) rf[i] = As[kk][f0 + i];
            #pragma unroll
            for (int j = 0; j < 8; j++) rm[j] = Bs[kk][m0 + j];
            #pragma unroll
            for (int i = 0; i < 8; i++)
                #pragma unroll
                for (int j = 0; j < 8; j++) acc[i][j] = fmaf(rf[i], rm[j], acc[i][j]);
        }
        __syncthreads();
    }

    float dm[8];
    #pragma unroll
    for (int j = 0; j < 8; j++) dm[j] = g_dinv[m0g + m0 + j];

    // g_YsT_h[f][g]  fp16 (MMA B operand)
    #pragma unroll
    for (int i = 0; i < 8; i++) {
        uint32_t t[4];
        #pragma unroll
        for (int j = 0; j < 8; j += 2) {
            __half2 h = __floats2half2_rn(acc[i][j] * dm[j], acc[i][j + 1] * dm[j + 1]);
            t[j >> 1] = reinterpret_cast<uint32_t&>(h);
        }
        size_t dst = (size_t)(f0 + i) * GTOT + m0g + m0;
        *reinterpret_cast<uint4*>(&g_YsT_h[dst]) = make_uint4(t[0], t[1], t[2], t[3]);
    }
    // g_Ysn[g][f]  fp32 (exact identity term)
    #pragma unroll
    for (int j = 0; j < 8; j++) {
        float4 u0, u1;
        u0.x = acc[0][j] * dm[j]; u0.y = acc[1][j] * dm[j];
        u0.z = acc[2][j] * dm[j]; u0.w = acc[3][j] * dm[j];
        u1.x = acc[4][j] * dm[j]; u1.y = acc[5][j] * dm[j];
        u1.z = acc[6][j] * dm[j]; u1.w = acc[7][j] * dm[j];
        size_t dst = (size_t)(m0g + m0 + j) * FF + f0;
        *reinterpret_cast<float4*>(&g_Ysn[dst])     = u0;
        *reinterpret_cast<float4*>(&g_Ysn[dst + 4]) = u1;
    }
}

// ---------------------------------------------------------------------------
// Kernel 3: out[b,n,:] = d_n * ( A[b,n,:] @ Ysd[b] + Ysd[b,n,:] )
//   Single-product fp16 mma.sync (m16n8k16), fp32 accumulate.
//   CTA 128x128, K-chunk 32, double-buffered smem.
//   8 warps = 2(m) x 4(n); warp tile 64x32 -> 4x4 m16n8k16 tiles.
// ---------------------------------------------------------------------------
#define PITCH 80                    // 32 fp16 = 64B data + 16B pad (16B-aligned rows)
#define TILE3 (128 * PITCH)         // 10240 per operand tile
#define BUF3  (2 * TILE3)           // A + B per stage = 20480
#define SMEM3 (2 * BUF3)            // 40960

__global__ void __launch_bounds__(256, 1) gemm_mma(const float* __restrict__ A,
                                                   float* __restrict__ out) {
    extern __shared__ char sm[];
    const uint32_t sb = smem_to_u32(sm);

    const int tid = threadIdx.x;
    const int wid = tid >> 5, lane = tid & 31;
    const int g = lane >> 2, tig = lane & 3;
    const int wm = wid & 1, wn = wid >> 1;
    const int b = blockIdx.y;
    const int rowStart = blockIdx.x * 128;

    // Staging mapping: row = tid>>1, half = tid&1 covers 16 of 32 k-values
    const int cr = tid >> 1;
    const int ch = tid & 1;
    const float*  Ap = A + ((size_t)b * NN + rowStart + cr) * NN + ch * 16;
    const __half* Bp = g_YsT_h + (size_t)cr * GTOT + (size_t)b * NN + ch * 16;
    const uint32_t sA = sb + cr * PITCH + ch * 32;            // fp16 dst (32B half-row)
    const uint32_t sB = sA + TILE3;

    float4 av[4];   // 16 fp32 A values held between ldg and sts

    auto cp_B = [&](int kc, int buf) {
        const uint32_t d = sB + buf * BUF3;
        const __half* p = Bp + kc * 32;
        CP_ASYNC_16(d, p);
        CP_ASYNC_16(d + 16, p + 8);
    };
    auto ldg_A = [&](int kc) {
        const float* p = Ap + kc * 32;
        #pragma unroll
        for (int j = 0; j < 4; j++) av[j] = *reinterpret_cast<const float4*>(p + j * 4);
    };
    auto sts_A = [&](int buf) {
        uint32_t t[8];
        #pragma unroll
        for (int j = 0; j < 4; j++) {
            __half2 h0 = __floats2half2_rn(av[j].x, av[j].y);
            __half2 h1 = __floats2half2_rn(av[j].z, av[j].w);
            t[j * 2]     = reinterpret_cast<uint32_t&>(h0);
            t[j * 2 + 1] = reinterpret_cast<uint32_t&>(h1);
        }
        const uint32_t d = sA + buf * BUF3;
        *reinterpret_cast<uint4*>(sm + (d - sb))      = make_uint4(t[0], t[1], t[2], t[3]);
        *reinterpret_cast<uint4*>(sm + (d - sb) + 16) = make_uint4(t[4], t[5], t[6], t[7]);
    };

    float acc[4][4][4];
    #pragma unroll
    for (int i = 0; i < 4; i++)
        #pragma unroll
        for (int j = 0; j < 4; j++)
            #pragma unroll
            for (int k = 0; k < 4; k++) acc[i][j][k] = 0.f;

    // Prologue: stage chunk 0 into buffer 0
    cp_B(0, 0);
    CP_ASYNC_COMMIT();
    ldg_A(0);
    sts_A(0);
    CP_ASYNC_WAIT_ALL();
    __syncthreads();

    for (int kc = 0; kc < NN / 32; kc++) {
        const int buf = kc & 1;
        const bool more = (kc + 1 < NN / 32);
        if (more) {
            cp_B(kc + 1, buf ^ 1);
            CP_ASYNC_COMMIT();
            ldg_A(kc + 1);
        }

        char* Ab = sm + buf * BUF3;
        char* Bb = Ab + TILE3;

        #pragma unroll
        for (int ks = 0; ks < 2; ks++) {
            const int kb = ks * 32 + tig * 4;
            uint32_t af[4][4], bf2[4][2];
            #pragma unroll
            for (int mt = 0; mt < 4; mt++) {
                const uint32_t o = (wm * 64 + mt * 16 + g) * PITCH + kb;
                af[mt][0] = *reinterpret_cast<uint32_t*>(Ab + o);
                af[mt][1] = *reinterpret_cast<uint32_t*>(Ab + o + 8 * PITCH);
                af[mt][2] = *reinterpret_cast<uint32_t*>(Ab + o + 16);
                af[mt][3] = *reinterpret_cast<uint32_t*>(Ab + o + 8 * PITCH + 16);
            }
            #pragma unroll
            for (int nt = 0; nt < 4; nt++) {
                const uint32_t o = (wn * 32 + nt * 8 + g) * PITCH + kb;
                bf2[nt][0] = *reinterpret_cast<uint32_t*>(Bb + o);
                bf2[nt][1] = *reinterpret_cast<uint32_t*>(Bb + o + 16);
            }
            #pragma unroll
            for (int mt = 0; mt < 4; mt++)
                #pragma unroll
                for (int nt = 0; nt < 4; nt++)
                    mma_f16(acc[mt][nt], af[mt], bf2[nt]);
        }

        if (more) sts_A(buf ^ 1);
        CP_ASYNC_WAIT_ALL();
        __syncthreads();
    }

    // Epilogue: out = d_n * (acc + Ysd[n,:])  — identity term exact in fp32
    #pragma unroll
    for (int mt = 0; mt < 4; mt++) {
        const int gr0 = b * NN + rowStart + wm * 64 + mt * 16 + g;
        const float d0 = g_dinv[gr0];
        const float d1 = g_dinv[gr0 + 8];
        const float* ys0 = g_Ysn + (size_t)gr0 * FF + wn * 32 + tig * 2;
        const float* ys1 = ys0 + (size_t)8 * FF;
        float* o0 = out + (size_t)gr0 * FF + wn * 32 + tig * 2;
        float* o1 = o0 + (size_t)8 * FF;
        #pragma unroll
        for (int nt = 0; nt < 4; nt++) {
            float2 y0 = *reinterpret_cast<const float2*>(ys0 + nt * 8);
            float2 y1 = *reinterpret_cast<const float2*>(ys1 + nt * 8);
            float2 v0, v1;
            v0.x = d0 * (acc[mt][nt][0] + y0.x);
            v0.y = d0 * (acc[mt][nt][1] + y0.y);
            v1.x = d1 * (acc[mt][nt][2] + y1.x);
            v1.y = d1 * (acc[mt][nt][3] + y1.y);
            *reinterpret_cast<float2*>(o0 + nt * 8) = v0;
            *reinterpret_cast<float2*>(o1 + nt * 8) = v1;
        }
    }
}

// ---------------------------------------------------------------------------
// kernel_launch
// ---------------------------------------------------------------------------
extern "C" void kernel_launch(void* const* d_in, const int* in_sizes, int n_in,
                              void* d_out, int out_size) {
    const float* X = (const float*)d_in[0];   // [16,1024,128]
    const float* A = (const float*)d_in[1];   // [16,1024,1024]
    const float* W = (const float*)d_in[2];   // [128,128]
    float* out = (float*)d_out;               // [16,1024,128]

    cudaFuncSetAttribute(gemm_mma, cudaFuncAttributeMaxDynamicSharedMemorySize, SMEM3);

    // 1) dinv = rsqrt(rowsum(A) + 1)
    deg_kernel<<<GTOT / 16, 256>>>(A);

    // 2) Ysd = d_m * (X @ W), dual layout (fp16 transposed + fp32 natural)
    gemm_xw_t<<<GTOT / 128, 256>>>(X, W);

    // 3) out = d_n * (A @ Ysd + Ysd[n,:])  via fp16 mma.sync
    {
        dim3 grid(NN / 128, BATCH);
        gemm_mma<<<grid, 256, SMEM3>>>(A, out);
    }
}

// round 7
// speedup vs baseline: 1.4065x; 1.1313x over previous
#include <cuda_runtime.h>
#include <cuda_fp16.h>
#include <cstdint>

// Problem constants
#define BATCH 16
#define NN    1024
#define FF    128
#define GTOT  (BATCH * NN)     // 16384

// ---------------------------------------------------------------------------
// Device-global scratch (no allocations allowed)
// ---------------------------------------------------------------------------
__device__ float  g_dinv[GTOT];             // 64 KB
__device__ __half g_YsT_h[FF * GTOT];       // 4 MB  [f][g]  fp16, d_m-scaled
__device__ float  g_Ysn[GTOT * FF];         // 8 MB  [g][f]  fp32, d_m-scaled

// ---------------------------------------------------------------------------
// Helpers
// ---------------------------------------------------------------------------
__device__ __forceinline__ uint32_t smem_to_u32(const void* p) {
    uint32_t a;
    asm("{ .reg .u64 t; cvta.to.shared.u64 t, %1; cvt.u32.u64 %0, t; }" : "=r"(a) : "l"(p));
    return a;
}
#define CP_ASYNC_16(dst_u32, src) \
    asm volatile("cp.async.cg.shared.global [%0], [%1], 16;" \
                 :: "r"(dst_u32), "l"(src) : "memory")
#define CP_ASYNC_COMMIT()  asm volatile("cp.async.commit_group;" ::: "memory")
#define CP_ASYNC_WAIT1()   asm volatile("cp.async.wait_group 1;" ::: "memory")
#define CP_ASYNC_WAIT0()   asm volatile("cp.async.wait_group 0;" ::: "memory")

__device__ __forceinline__ void mma_f16(float* c, const uint32_t* a, const uint32_t* b) {
    asm volatile(
        "mma.sync.aligned.m16n8k16.row.col.f32.f16.f16.f32 "
        "{%0,%1,%2,%3}, {%4,%5,%6,%7}, {%8,%9}, {%0,%1,%2,%3};\n"
        : "+f"(c[0]), "+f"(c[1]), "+f"(c[2]), "+f"(c[3])
        : "r"(a[0]), "r"(a[1]), "r"(a[2]), "r"(a[3]), "r"(b[0]), "r"(b[1]));
}
__device__ __forceinline__ uint32_t pack_h2(float x, float y) {
    __half2 h = __floats2half2_rn(x, y);
    return reinterpret_cast<uint32_t&>(h);
}

// ---------------------------------------------------------------------------
// Kernel 1: dinv[row] = rsqrt( rowsum(A) + 1 ).  2 rows per warp, MLP=16.
// ---------------------------------------------------------------------------
__global__ void __launch_bounds__(256) deg_kernel(const float* __restrict__ A) {
    const int wid = threadIdx.x >> 5, lid = threadIdx.x & 31;
    const int row0 = blockIdx.x * 16 + wid * 2;
    const float4* r0 = reinterpret_cast<const float4*>(A + (size_t)row0 * NN);
    const float4* r1 = reinterpret_cast<const float4*>(A + (size_t)(row0 + 1) * NN);
    float s0 = 0.f, s1 = 0.f;
    #pragma unroll
    for (int i = 0; i < 8; i++) {
        float4 a = r0[lid + i * 32];
        float4 b = r1[lid + i * 32];
        s0 += (a.x + a.y) + (a.z + a.w);
        s1 += (b.x + b.y) + (b.z + b.w);
    }
    #pragma unroll
    for (int o = 16; o; o >>= 1) {
        s0 += __shfl_xor_sync(0xFFFFFFFFu, s0, o);
        s1 += __shfl_xor_sync(0xFFFFFFFFu, s1, o);
    }
    if (lid == 0) {
        g_dinv[row0]     = rsqrtf(s0 + 1.0f);
        g_dinv[row0 + 1] = rsqrtf(s1 + 1.0f);
    }
}

// ---------------------------------------------------------------------------
// Kernel 2: Ysd = d_m * (X @ W) via fp16 mma.sync, dual-layout output.
//   CTA: 128 g-rows x 128 f, K=128 one shot.  grid = 128, block = 256.
//   Smem: Xs[g][k] fp16 (pitch 272), Ws[f][k] fp16 (pitch 272, W transposed).
// ---------------------------------------------------------------------------
#define P2 272
#define XS_SZ (128 * P2)            // 34816
#define SMEM2 (2 * XS_SZ)           // 69632

__global__ void __launch_bounds__(256) gemm_xw_t(const float* __restrict__ X,
                                                 const float* __restrict__ W) {
    extern __shared__ char sm2[];
    char* Xs = sm2;
    char* Ws = sm2 + XS_SZ;

    const int tid = threadIdx.x;
    const int wid = tid >> 5, lane = tid & 31;
    const int g = lane >> 2, tig = lane & 3;
    const int wm = wid & 1, wn = wid >> 1;
    const int m0g = blockIdx.x * 128;

    // Stage W transposed: Ws[f][k] = W[k][f]   (fp16)
    for (int idx = tid; idx < 128 * 128; idx += 256) {
        int k = idx >> 7, f = idx & 127;
        float w = W[idx];
        *reinterpret_cast<__half*>(Ws + f * P2 + k * 2) = __float2half_rn(w);
    }
    // Stage X: Xs[g][k]  (fp16, k-contiguous)
    {
        const int r = tid >> 1, half = tid & 1;
        const float* xp = X + (size_t)(m0g + r) * FF + half * 64;
        char* dst = Xs + r * P2 + half * 128;
        #pragma unroll
        for (int j = 0; j < 8; j++) {
            float4 v0 = *reinterpret_cast<const float4*>(xp + j * 8);
            float4 v1 = *reinterpret_cast<const float4*>(xp + j * 8 + 4);
            uint4 o;
            o.x = pack_h2(v0.x, v0.y); o.y = pack_h2(v0.z, v0.w);
            o.z = pack_h2(v1.x, v1.y); o.w = pack_h2(v1.z, v1.w);
            *reinterpret_cast<uint4*>(dst + j * 16) = o;
        }
    }
    __syncthreads();

    float acc[4][4][4];
    #pragma unroll
    for (int i = 0; i < 4; i++)
        #pragma unroll
        for (int j = 0; j < 4; j++)
            #pragma unroll
            for (int k = 0; k < 4; k++) acc[i][j][k] = 0.f;

    #pragma unroll
    for (int ks = 0; ks < 8; ks++) {
        const int kb = ks * 32 + tig * 4;
        uint32_t af[4][4], bf2[4][2];
        #pragma unroll
        for (int mt = 0; mt < 4; mt++) {
            char* p = Xs + (wm * 64 + mt * 16 + g) * P2 + kb;
            af[mt][0] = *reinterpret_cast<uint32_t*>(p);
            af[mt][1] = *reinterpret_cast<uint32_t*>(p + 8 * P2);
            af[mt][2] = *reinterpret_cast<uint32_t*>(p + 16);
            af[mt][3] = *reinterpret_cast<uint32_t*>(p + 8 * P2 + 16);
        }
        #pragma unroll
        for (int nt = 0; nt < 4; nt++) {
            char* p = Ws + (wn * 32 + nt * 8 + g) * P2 + kb;
            bf2[nt][0] = *reinterpret_cast<uint32_t*>(p);
            bf2[nt][1] = *reinterpret_cast<uint32_t*>(p + 16);
        }
        #pragma unroll
        for (int mt = 0; mt < 4; mt++)
            #pragma unroll
            for (int nt = 0; nt < 4; nt++)
                mma_f16(acc[mt][nt], af[mt], bf2[nt]);
    }
    __syncthreads();   // Xs reused below for the transposed fp16 staging

    // Write fragments: scale by d_m, emit g_Ysn directly; stage Os[f][g] in smem
    char* Os = Xs;     // 128 f-rows x 128 g fp16, pitch P2
    #pragma unroll
    for (int mt = 0; mt < 4; mt++) {
        const int gl0 = wm * 64 + mt * 16 + g;
        const int gg0 = m0g + gl0;
        const float d0 = g_dinv[gg0];
        const float d1 = g_dinv[gg0 + 8];
        #pragma unroll
        for (int nt = 0; nt < 4; nt++) {
            const int f = wn * 32 + nt * 8 + tig * 2;
            float c0 = acc[mt][nt][0] * d0, c1 = acc[mt][nt][1] * d0;
            float c2 = acc[mt][nt][2] * d1, c3 = acc[mt][nt][3] * d1;
            *reinterpret_cast<float2*>(&g_Ysn[(size_t)gg0 * FF + f]) = make_float2(c0, c1);
            *reinterpret_cast<float2*>(&g_Ysn[(size_t)(gg0 + 8) * FF + f]) = make_float2(c2, c3);
            *reinterpret_cast<__half*>(Os + f * P2 + gl0 * 2)           = __float2half_rn(c0);
            *reinterpret_cast<__half*>(Os + (f + 1) * P2 + gl0 * 2)     = __float2half_rn(c1);
            *reinterpret_cast<__half*>(Os + f * P2 + (gl0 + 8) * 2)     = __float2half_rn(c2);
            *reinterpret_cast<__half*>(Os + (f + 1) * P2 + (gl0 + 8) * 2) = __float2half_rn(c3);
        }
    }
    __syncthreads();

    // Coalesced write of transposed fp16: g_YsT_h[f][m0g + g]
    {
        const int f = tid >> 1, half = tid & 1;
        char* src = Os + f * P2 + half * 128;
        __half* dst = g_YsT_h + (size_t)f * GTOT + m0g + half * 64;
        #pragma unroll
        for (int j = 0; j < 8; j++)
            *reinterpret_cast<uint4*>(dst + j * 8) = *reinterpret_cast<uint4*>(src + j * 16);
    }
}

// ---------------------------------------------------------------------------
// Kernel 3: out[b,n,:] = d_n * ( A[b,n,:] @ Ysd[b] + Ysd[b,n,:] )
//   fp16 mma.sync m16n8k16, fp32 accumulate.  CTA 128x128, K-chunk 64,
//   3-stage cp.async pipeline (A staged fp32, converted in fragment path).
// ---------------------------------------------------------------------------
#define PA 288                      // 64 fp32 = 256B + 32B pad (LDS.64 bank-clean)
#define PB 144                      // 64 fp16 = 128B + 16B pad (LDS.32 bank-clean)
#define TA (128 * PA)               // 36864
#define TB (128 * PB)               // 18432
#define STG3 (TA + TB)              // 55296
#define NSTAGE 3
#define SMEM3 (NSTAGE * STG3)       // 165888
#define NCHUNK (NN / 64)            // 16

__global__ void __launch_bounds__(256, 1) gemm_mma(const float* __restrict__ A,
                                                   float* __restrict__ out) {
    extern __shared__ char sm[];
    const uint32_t sb = smem_to_u32(sm);

    const int tid = threadIdx.x;
    const int wid = tid >> 5, lane = tid & 31;
    const int g = lane >> 2, tig = lane & 3;
    const int wm = wid & 1, wn = wid >> 1;
    const int b = blockIdx.y;
    const int rowStart = blockIdx.x * 128;

    // cp.async mapping: row = tid>>1, half = tid&1 (32 of 64 k-values)
    const int cr = tid >> 1;
    const int ch = tid & 1;
    const float*  Ap = A + ((size_t)b * NN + rowStart + cr) * NN + ch * 32;
    const __half* Bp = g_YsT_h + (size_t)cr * GTOT + (size_t)b * NN + ch * 32;
    const uint32_t dA0 = sb + cr * PA + ch * 128;
    const uint32_t dB0 = sb + TA + cr * PB + ch * 64;

    auto issue = [&](int kc) {
        const uint32_t s = (kc % NSTAGE) * STG3;
        const float*  pa = Ap + kc * 64;
        const __half* pb = Bp + kc * 64;
        #pragma unroll
        for (int j = 0; j < 8; j++) CP_ASYNC_16(dA0 + s + j * 16, pa + j * 4);
        #pragma unroll
        for (int j = 0; j < 4; j++) CP_ASYNC_16(dB0 + s + j * 16, pb + j * 8);
        CP_ASYNC_COMMIT();
    };

    float acc[4][4][4];
    #pragma unroll
    for (int i = 0; i < 4; i++)
        #pragma unroll
        for (int j = 0; j < 4; j++)
            #pragma unroll
            for (int k = 0; k < 4; k++) acc[i][j][k] = 0.f;

    issue(0);
    issue(1);

    for (int kc = 0; kc < NCHUNK; kc++) {
        if (kc < NCHUNK - 1) { CP_ASYNC_WAIT1(); } else { CP_ASYNC_WAIT0(); }
        __syncthreads();
        if (kc + 2 < NCHUNK) issue(kc + 2);

        char* Ab = sm + (kc % NSTAGE) * STG3;
        char* Bb = Ab + TA;

        #pragma unroll
        for (int ks = 0; ks < 4; ks++) {
            uint32_t af[4][4], bf2[4][2];
            #pragma unroll
            for (int mt = 0; mt < 4; mt++) {
                char* p = Ab + (wm * 64 + mt * 16 + g) * PA + ks * 64 + tig * 8;
                float2 f0 = *reinterpret_cast<float2*>(p);
                float2 f1 = *reinterpret_cast<float2*>(p + 8 * PA);
                float2 f2 = *reinterpret_cast<float2*>(p + 32);
                float2 f3 = *reinterpret_cast<float2*>(p + 8 * PA + 32);
                af[mt][0] = pack_h2(f0.x, f0.y);
                af[mt][1] = pack_h2(f1.x, f1.y);
                af[mt][2] = pack_h2(f2.x, f2.y);
                af[mt][3] = pack_h2(f3.x, f3.y);
            }
            #pragma unroll
            for (int nt = 0; nt < 4; nt++) {
                char* p = Bb + (wn * 32 + nt * 8 + g) * PB + ks * 32 + tig * 4;
                bf2[nt][0] = *reinterpret_cast<uint32_t*>(p);
                bf2[nt][1] = *reinterpret_cast<uint32_t*>(p + 16);
            }
            #pragma unroll
            for (int mt = 0; mt < 4; mt++)
                #pragma unroll
                for (int nt = 0; nt < 4; nt++)
                    mma_f16(acc[mt][nt], af[mt], bf2[nt]);
        }
    }

    // Epilogue: out = d_n * (acc + Ysd[n,:])  — identity term exact in fp32
    #pragma unroll
    for (int mt = 0; mt < 4; mt++) {
        const int gr0 = b * NN + rowStart + wm * 64 + mt * 16 + g;
        const float d0 = g_dinv[gr0];
        const float d1 = g_dinv[gr0 + 8];
        const float* ys0 = g_Ysn + (size_t)gr0 * FF + wn * 32 + tig * 2;
        const float* ys1 = ys0 + (size_t)8 * FF;
        float* o0 = out + (size_t)gr0 * FF + wn * 32 + tig * 2;
        float* o1 = o0 + (size_t)8 * FF;
        #pragma unroll
        for (int nt = 0; nt < 4; nt++) {
            float2 y0 = *reinterpret_cast<const float2*>(ys0 + nt * 8);
            float2 y1 = *reinterpret_cast<const float2*>(ys1 + nt * 8);
            float2 v0, v1;
            v0.x = d0 * (acc[mt][nt][0] + y0.x);
            v0.y = d0 * (acc[mt][nt][1] + y0.y);
            v1.x = d1 * (acc[mt][nt][2] + y1.x);
            v1.y = d1 * (acc[mt][nt][3] + y1.y);
            *reinterpret_cast<float2*>(o0 + nt * 8) = v0;
            *reinterpret_cast<float2*>(o1 + nt * 8) = v1;
        }
    }
}

// ---------------------------------------------------------------------------
// kernel_launch
// ---------------------------------------------------------------------------
extern "C" void kernel_launch(void* const* d_in, const int* in_sizes, int n_in,
                              void* d_out, int out_size) {
    const float* X = (const float*)d_in[0];   // [16,1024,128]
    const float* A = (const float*)d_in[1];   // [16,1024,1024]
    const float* W = (const float*)d_in[2];   // [128,128]
    float* out = (float*)d_out;               // [16,1024,128]

    cudaFuncSetAttribute(gemm_xw_t, cudaFuncAttributeMaxDynamicSharedMemorySize, SMEM2);
    cudaFuncSetAttribute(gemm_mma, cudaFuncAttributeMaxDynamicSharedMemorySize, SMEM3);

    // 1) dinv = rsqrt(rowsum(A) + 1)
    deg_kernel<<<GTOT / 16, 256>>>(A);

    // 2) Ysd = d_m * (X @ W) via fp16 MMA, dual layout
    gemm_xw_t<<<GTOT / 128, 256, SMEM2>>>(X, W);

    // 3) out = d_n * (A @ Ysd + Ysd[n,:])  via fp16 mma.sync, 3-stage pipeline
    {
        dim3 grid(NN / 128, BATCH);
        gemm_mma<<<grid, 256, SMEM3>>>(A, out);
    }
}

// round 8
// speedup vs baseline: 1.4603x; 1.0382x over previous
#include <cuda_runtime.h>
#include <cuda_fp16.h>
#include <cstdint>

// Problem constants
#define BATCH 16
#define NN    1024
#define FF    128
#define GTOT  (BATCH * NN)     // 16384

// ---------------------------------------------------------------------------
// Device-global scratch (no allocations allowed)
// ---------------------------------------------------------------------------
__device__ float  g_dinv[GTOT];             // 64 KB
__device__ __half g_Ah[(size_t)GTOT * NN];  // 32 MB  A in fp16, natural layout
__device__ __half g_YsT_h[FF * GTOT];       // 4 MB   [f][g] fp16, d_m-scaled
__device__ float  g_Ysn[GTOT * FF];         // 8 MB   [g][f] fp32, d_m-scaled

// ---------------------------------------------------------------------------
// Helpers
// ---------------------------------------------------------------------------
__device__ __forceinline__ uint32_t smem_to_u32(const void* p) {
    uint32_t a;
    asm("{ .reg .u64 t; cvta.to.shared.u64 t, %1; cvt.u32.u64 %0, t; }" : "=r"(a) : "l"(p));
    return a;
}
#define CP_ASYNC_16(dst_u32, src) \
    asm volatile("cp.async.cg.shared.global [%0], [%1], 16;" \
                 :: "r"(dst_u32), "l"(src) : "memory")
#define CP_ASYNC_COMMIT()  asm volatile("cp.async.commit_group;" ::: "memory")
#define CP_ASYNC_WAIT1()   asm volatile("cp.async.wait_group 1;" ::: "memory")
#define CP_ASYNC_WAIT0()   asm volatile("cp.async.wait_group 0;" ::: "memory")

#define LDSM_X4(r0, r1, r2, r3, addr) \
    asm volatile("ldmatrix.sync.aligned.m8n8.x4.shared.b16 {%0,%1,%2,%3}, [%4];" \
                 : "=r"(r0), "=r"(r1), "=r"(r2), "=r"(r3) : "r"(addr))

__device__ __forceinline__ void mma_f16(float* c, const uint32_t* a, const uint32_t* b) {
    asm volatile(
        "mma.sync.aligned.m16n8k16.row.col.f32.f16.f16.f32 "
        "{%0,%1,%2,%3}, {%4,%5,%6,%7}, {%8,%9}, {%0,%1,%2,%3};\n"
        : "+f"(c[0]), "+f"(c[1]), "+f"(c[2]), "+f"(c[3])
        : "r"(a[0]), "r"(a[1]), "r"(a[2]), "r"(a[3]), "r"(b[0]), "r"(b[1]));
}
__device__ __forceinline__ uint32_t pack_h2(float x, float y) {
    __half2 h = __floats2half2_rn(x, y);
    return reinterpret_cast<uint32_t&>(h);
}

// ---------------------------------------------------------------------------
// Kernel 1: dinv[row] = rsqrt(rowsum(A)+1)  AND  g_Ah = fp16(A)  (fused)
//   Warp covers 2 rows; per row 8 float4 loads + 8 uint2 fp16 stores.
// ---------------------------------------------------------------------------
__global__ void __launch_bounds__(256) deg_kernel(const float* __restrict__ A) {
    const int wid = threadIdx.x >> 5, lid = threadIdx.x & 31;
    const int row0 = blockIdx.x * 16 + wid * 2;
    const float4* r0 = reinterpret_cast<const float4*>(A + (size_t)row0 * NN);
    const float4* r1 = reinterpret_cast<const float4*>(A + (size_t)(row0 + 1) * NN);
    __half* h0 = g_Ah + (size_t)row0 * NN;
    __half* h1 = h0 + NN;
    float s0 = 0.f, s1 = 0.f;
    #pragma unroll
    for (int i = 0; i < 8; i++) {
        float4 a = r0[lid + i * 32];
        float4 b = r1[lid + i * 32];
        s0 += (a.x + a.y) + (a.z + a.w);
        s1 += (b.x + b.y) + (b.z + b.w);
        uint2 pa = make_uint2(pack_h2(a.x, a.y), pack_h2(a.z, a.w));
        uint2 pb = make_uint2(pack_h2(b.x, b.y), pack_h2(b.z, b.w));
        *reinterpret_cast<uint2*>(h0 + (lid + i * 32) * 4) = pa;
        *reinterpret_cast<uint2*>(h1 + (lid + i * 32) * 4) = pb;
    }
    #pragma unroll
    for (int o = 16; o; o >>= 1) {
        s0 += __shfl_xor_sync(0xFFFFFFFFu, s0, o);
        s1 += __shfl_xor_sync(0xFFFFFFFFu, s1, o);
    }
    if (lid == 0) {
        g_dinv[row0]     = rsqrtf(s0 + 1.0f);
        g_dinv[row0 + 1] = rsqrtf(s1 + 1.0f);
    }
}

// ---------------------------------------------------------------------------
// Kernel 2: Ysd = d_m * (X @ W) via fp16 mma.sync, dual-layout output.
//   (unchanged from R7: ~5 us)
// ---------------------------------------------------------------------------
#define P2 272
#define XS_SZ (128 * P2)
#define SMEM2 (2 * XS_SZ)

__global__ void __launch_bounds__(256) gemm_xw_t(const float* __restrict__ X,
                                                 const float* __restrict__ W) {
    extern __shared__ char sm2[];
    char* Xs = sm2;
    char* Ws = sm2 + XS_SZ;

    const int tid = threadIdx.x;
    const int wid = tid >> 5, lane = tid & 31;
    const int g = lane >> 2, tig = lane & 3;
    const int wm = wid & 1, wn = wid >> 1;
    const int m0g = blockIdx.x * 128;

    for (int idx = tid; idx < 128 * 128; idx += 256) {
        int k = idx >> 7, f = idx & 127;
        float w = W[idx];
        *reinterpret_cast<__half*>(Ws + f * P2 + k * 2) = __float2half_rn(w);
    }
    {
        const int r = tid >> 1, half = tid & 1;
        const float* xp = X + (size_t)(m0g + r) * FF + half * 64;
        char* dst = Xs + r * P2 + half * 128;
        #pragma unroll
        for (int j = 0; j < 8; j++) {
            float4 v0 = *reinterpret_cast<const float4*>(xp + j * 8);
            float4 v1 = *reinterpret_cast<const float4*>(xp + j * 8 + 4);
            uint4 o;
            o.x = pack_h2(v0.x, v0.y); o.y = pack_h2(v0.z, v0.w);
            o.z = pack_h2(v1.x, v1.y); o.w = pack_h2(v1.z, v1.w);
            *reinterpret_cast<uint4*>(dst + j * 16) = o;
        }
    }
    __syncthreads();

    float acc[4][4][4];
    #pragma unroll
    for (int i = 0; i < 4; i++)
        #pragma unroll
        for (int j = 0; j < 4; j++)
            #pragma unroll
            for (int k = 0; k < 4; k++) acc[i][j][k] = 0.f;

    #pragma unroll
    for (int ks = 0; ks < 8; ks++) {
        const int kb = ks * 32 + tig * 4;
        uint32_t af[4][4], bf2[4][2];
        #pragma unroll
        for (int mt = 0; mt < 4; mt++) {
            char* p = Xs + (wm * 64 + mt * 16 + g) * P2 + kb;
            af[mt][0] = *reinterpret_cast<uint32_t*>(p);
            af[mt][1] = *reinterpret_cast<uint32_t*>(p + 8 * P2);
            af[mt][2] = *reinterpret_cast<uint32_t*>(p + 16);
            af[mt][3] = *reinterpret_cast<uint32_t*>(p + 8 * P2 + 16);
        }
        #pragma unroll
        for (int nt = 0; nt < 4; nt++) {
            char* p = Ws + (wn * 32 + nt * 8 + g) * P2 + kb;
            bf2[nt][0] = *reinterpret_cast<uint32_t*>(p);
            bf2[nt][1] = *reinterpret_cast<uint32_t*>(p + 16);
        }
        #pragma unroll
        for (int mt = 0; mt < 4; mt++)
            #pragma unroll
            for (int nt = 0; nt < 4; nt++)
                mma_f16(acc[mt][nt], af[mt], bf2[nt]);
    }
    __syncthreads();

    char* Os = Xs;
    #pragma unroll
    for (int mt = 0; mt < 4; mt++) {
        const int gl0 = wm * 64 + mt * 16 + g;
        const int gg0 = m0g + gl0;
        const float d0 = g_dinv[gg0];
        const float d1 = g_dinv[gg0 + 8];
        #pragma unroll
        for (int nt = 0; nt < 4; nt++) {
            const int f = wn * 32 + nt * 8 + tig * 2;
            float c0 = acc[mt][nt][0] * d0, c1 = acc[mt][nt][1] * d0;
            float c2 = acc[mt][nt][2] * d1, c3 = acc[mt][nt][3] * d1;
            *reinterpret_cast<float2*>(&g_Ysn[(size_t)gg0 * FF + f]) = make_float2(c0, c1);
            *reinterpret_cast<float2*>(&g_Ysn[(size_t)(gg0 + 8) * FF + f]) = make_float2(c2, c3);
            *reinterpret_cast<__half*>(Os + f * P2 + gl0 * 2)             = __float2half_rn(c0);
            *reinterpret_cast<__half*>(Os + (f + 1) * P2 + gl0 * 2)       = __float2half_rn(c1);
            *reinterpret_cast<__half*>(Os + f * P2 + (gl0 + 8) * 2)       = __float2half_rn(c2);
            *reinterpret_cast<__half*>(Os + (f + 1) * P2 + (gl0 + 8) * 2) = __float2half_rn(c3);
        }
    }
    __syncthreads();
    {
        const int f = tid >> 1, half = tid & 1;
        char* src = Os + f * P2 + half * 128;
        __half* dst = g_YsT_h + (size_t)f * GTOT + m0g + half * 64;
        #pragma unroll
        for (int j = 0; j < 8; j++)
            *reinterpret_cast<uint4*>(dst + j * 8) = *reinterpret_cast<uint4*>(src + j * 16);
    }
}

// ---------------------------------------------------------------------------
// Kernel 3: out[b,n,:] = d_n * ( A[b,n,:] @ Ysd[b] + Ysd[b,n,:] )
//   fp16 A (pre-converted) + fp16 B, ldmatrix fragment loads, fp32 accum.
//   CTA 128x128, K-chunk 64, 3-stage cp.async pipeline.
// ---------------------------------------------------------------------------
#define PA3 144                     // 64 fp16 = 128B + 16B pad (LDSM conflict-free)
#define TA3 (128 * PA3)             // 18432
#define STG3 (2 * TA3)              // 36864 (A + B per stage)
#define NSTAGE 3
#define SMEM3 (NSTAGE * STG3)       // 110592
#define NCHUNK (NN / 64)            // 16

__global__ void __launch_bounds__(256, 1) gemm_mma(float* __restrict__ out) {
    extern __shared__ char sm[];
    const uint32_t sb = smem_to_u32(sm);

    const int tid = threadIdx.x;
    const int wid = tid >> 5, lane = tid & 31;
    const int g = lane >> 2, tig = lane & 3;
    const int wm = wid & 1, wn = wid >> 1;
    const int b = blockIdx.y;
    const int rowStart = blockIdx.x * 128;

    // cp.async mapping: row = tid>>1, half = tid&1 (32 of 64 k-values, 64B)
    const int cr = tid >> 1;
    const int ch = tid & 1;
    const __half* Ap = g_Ah + ((size_t)b * NN + rowStart + cr) * NN + ch * 32;
    const __half* Bp = g_YsT_h + (size_t)cr * GTOT + (size_t)b * NN + ch * 32;
    const uint32_t dA0 = sb + cr * PA3 + ch * 64;
    const uint32_t dB0 = dA0 + TA3;

    auto issue = [&](int kc) {
        const uint32_t s = (kc % NSTAGE) * STG3;
        const __half* pa = Ap + kc * 64;
        const __half* pb = Bp + kc * 64;
        #pragma unroll
        for (int j = 0; j < 4; j++) CP_ASYNC_16(dA0 + s + j * 16, pa + j * 8);
        #pragma unroll
        for (int j = 0; j < 4; j++) CP_ASYNC_16(dB0 + s + j * 16, pb + j * 8);
        CP_ASYNC_COMMIT();
    };

    // ldmatrix lane addressing
    const int t = lane >> 3, r8 = lane & 7;
    // A x4 tiles: (m0,k0),(m0+8,k0),(m0,k0+8),(m0+8,k0+8)
    const uint32_t aOff = (uint32_t)(wm * 64 + (t & 1) * 8 + r8) * PA3 + ((t >> 1) * 8) * 2;
    // B x4 tiles (n-pair): (n0,k0),(n0,k0+8),(n0+8,k0),(n0+8,k0+8)
    const uint32_t bOff = TA3 + (uint32_t)(wn * 32 + (t >> 1) * 8 + r8) * PA3 + ((t & 1) * 8) * 2;

    float acc[4][4][4];
    #pragma unroll
    for (int i = 0; i < 4; i++)
        #pragma unroll
        for (int j = 0; j < 4; j++)
            #pragma unroll
            for (int k = 0; k < 4; k++) acc[i][j][k] = 0.f;

    issue(0);
    issue(1);

    for (int kc = 0; kc < NCHUNK; kc++) {
        if (kc < NCHUNK - 1) { CP_ASYNC_WAIT1(); } else { CP_ASYNC_WAIT0(); }
        __syncthreads();
        if (kc + 2 < NCHUNK) issue(kc + 2);

        const uint32_t st = sb + (kc % NSTAGE) * STG3;

        #pragma unroll
        for (int ks = 0; ks < 4; ks++) {
            uint32_t af[4][4], bf2[4][2];
            #pragma unroll
            for (int mt = 0; mt < 4; mt++)
                LDSM_X4(af[mt][0], af[mt][1], af[mt][2], af[mt][3],
                        st + aOff + (uint32_t)mt * 16 * PA3 + ks * 32);
            #pragma unroll
            for (int np = 0; np < 2; np++)
                LDSM_X4(bf2[np * 2][0], bf2[np * 2][1], bf2[np * 2 + 1][0], bf2[np * 2 + 1][1],
                        st + bOff + (uint32_t)np * 16 * PA3 + ks * 32);
            #pragma unroll
            for (int mt = 0; mt < 4; mt++)
                #pragma unroll
                for (int nt = 0; nt < 4; nt++)
                    mma_f16(acc[mt][nt], af[mt], bf2[nt]);
        }
    }

    // Epilogue: out = d_n * (acc + Ysd[n,:])  — identity term exact in fp32
    #pragma unroll
    for (int mt = 0; mt < 4; mt++) {
        const int gr0 = b * NN + rowStart + wm * 64 + mt * 16 + g;
        const float d0 = g_dinv[gr0];
        const float d1 = g_dinv[gr0 + 8];
        const float* ys0 = g_Ysn + (size_t)gr0 * FF + wn * 32 + tig * 2;
        const float* ys1 = ys0 + (size_t)8 * FF;
        float* o0 = out + (size_t)gr0 * FF + wn * 32 + tig * 2;
        float* o1 = o0 + (size_t)8 * FF;
        #pragma unroll
        for (int nt = 0; nt < 4; nt++) {
            float2 y0 = *reinterpret_cast<const float2*>(ys0 + nt * 8);
            float2 y1 = *reinterpret_cast<const float2*>(ys1 + nt * 8);
            float2 v0, v1;
            v0.x = d0 * (acc[mt][nt][0] + y0.x);
            v0.y = d0 * (acc[mt][nt][1] + y0.y);
            v1.x = d1 * (acc[mt][nt][2] + y1.x);
            v1.y = d1 * (acc[mt][nt][3] + y1.y);
            *reinterpret_cast<float2*>(o0 + nt * 8) = v0;
            *reinterpret_cast<float2*>(o1 + nt * 8) = v1;
        }
    }
}

// ---------------------------------------------------------------------------
// kernel_launch
// ---------------------------------------------------------------------------
extern "C" void kernel_launch(void* const* d_in, const int* in_sizes, int n_in,
                              void* d_out, int out_size) {
    const float* X = (const float*)d_in[0];   // [16,1024,128]
    const float* A = (const float*)d_in[1];   // [16,1024,1024]
    const float* W = (const float*)d_in[2];   // [128,128]
    float* out = (float*)d_out;               // [16,1024,128]

    cudaFuncSetAttribute(gemm_xw_t, cudaFuncAttributeMaxDynamicSharedMemorySize, SMEM2);
    cudaFuncSetAttribute(gemm_mma, cudaFuncAttributeMaxDynamicSharedMemorySize, SMEM3);

    // 1) dinv = rsqrt(rowsum(A)+1)  +  A -> fp16 (fused)
    deg_kernel<<<GTOT / 16, 256>>>(A);

    // 2) Ysd = d_m * (X @ W) via fp16 MMA, dual layout
    gemm_xw_t<<<GTOT / 128, 256, SMEM2>>>(X, W);

    // 3) out = d_n * (A @ Ysd + Ysd[n,:])  via ldmatrix + fp16 mma.sync
    {
        dim3 grid(NN / 128, BATCH);
        gemm_mma<<<grid, 256, SMEM3>>>(out);
    }
}